// round 5
// baseline (speedup 1.0000x reference)
#include <cuda_runtime.h>
#include <cuda_fp16.h>
#include <cstdint>

#define Bb 2
#define Ts 2048
#define Cc 1024
#define Hh 16
#define Dh 64
#define MROWS (Bb*Ts)   // 4096
#define SCALE 0.125f
#define LOG2E 1.4426950408889634f
#define WELEM (Cc*Cc)

// Scratch (allocation-free rule: __device__ globals)
__device__ __align__(16) __half g_xh[MROWS*Cc];
__device__ __align__(16) __half g_wh[4*WELEM];          // Wk, Wq, Wv, Wp (fp16)
__device__ __align__(16) __half g_qh[Bb*Hh*Ts*Dh];      // [b,h,t,d], pre-scaled by log2e/8
__device__ __align__(16) __half g_kh[Bb*Hh*Ts*Dh];
__device__ __align__(16) __half g_vh[Bb*Hh*Ts*Dh];
__device__ __align__(16) __half g_yh[MROWS*Cc];

__device__ __forceinline__ void cp16(uint32_t dst, const void* src) {
    asm volatile("cp.async.cg.shared.global [%0], [%1], 16;\n" :: "r"(dst), "l"(src));
}
__device__ __forceinline__ void cp_commit() { asm volatile("cp.async.commit_group;\n"); }
template<int N> __device__ __forceinline__ void cp_wait() {
    asm volatile("cp.async.wait_group %0;\n" :: "n"(N));
}
__device__ __forceinline__ void ldsm4(uint32_t& r0, uint32_t& r1, uint32_t& r2, uint32_t& r3, uint32_t a) {
    asm volatile("ldmatrix.sync.aligned.m8n8.x4.shared.b16 {%0,%1,%2,%3}, [%4];\n"
                 : "=r"(r0), "=r"(r1), "=r"(r2), "=r"(r3) : "r"(a));
}
__device__ __forceinline__ void ldsm4t(uint32_t& r0, uint32_t& r1, uint32_t& r2, uint32_t& r3, uint32_t a) {
    asm volatile("ldmatrix.sync.aligned.m8n8.x4.trans.shared.b16 {%0,%1,%2,%3}, [%4];\n"
                 : "=r"(r0), "=r"(r1), "=r"(r2), "=r"(r3) : "r"(a));
}
__device__ __forceinline__ void mma16816(float* c, const uint32_t* a, uint32_t b0, uint32_t b1) {
    asm volatile("mma.sync.aligned.m16n8k16.row.col.f32.f16.f16.f32 "
                 "{%0,%1,%2,%3}, {%4,%5,%6,%7}, {%8,%9}, {%0,%1,%2,%3};\n"
                 : "+f"(c[0]), "+f"(c[1]), "+f"(c[2]), "+f"(c[3])
                 : "r"(a[0]), "r"(a[1]), "r"(a[2]), "r"(a[3]), "r"(b0), "r"(b1));
}
__device__ __forceinline__ float dexp2(float x) {
    float r;
    asm("ex2.approx.f32 %0, %1;" : "=f"(r) : "f"(x));
    return r;
}

// ---------------- f32 -> f16 preconversion (single launch) ----------------
__global__ void f2h_all(const float* __restrict__ x,  const float* __restrict__ wk,
                        const float* __restrict__ wq, const float* __restrict__ wv,
                        const float* __restrict__ wp, int nx8, int nw8) {
    int i = blockIdx.x * blockDim.x + threadIdx.x;
    const float* s;
    __half* d;
    int off;
    if (i < nx8) { s = x; d = g_xh; off = i; }
    else {
        int j = i - nx8;
        int which = j / nw8;           // 0..3 (power-of-2 divide)
        off = j - which * nw8;
        s = (which == 0) ? wk : (which == 1) ? wq : (which == 2) ? wv : wp;
        d = g_wh + (size_t)which * WELEM;
    }
    float4 a = reinterpret_cast<const float4*>(s)[2*off];
    float4 b = reinterpret_cast<const float4*>(s)[2*off+1];
    __half2* d2 = reinterpret_cast<__half2*>(d) + 4*off;
    d2[0] = __floats2half2_rn(a.x, a.y);
    d2[1] = __floats2half2_rn(a.z, a.w);
    d2[2] = __floats2half2_rn(b.x, b.y);
    d2[3] = __floats2half2_rn(b.z, b.w);
}

// ---------------- fp16 GEMM: out = A[M,K] @ W[N,K]^T ----------------
// Block 128x128, BK=32 halves, 3-stage cp.async (1 sync/iter), 8 warps 2(M)x4(N).
template<int MODE>
__global__ __launch_bounds__(256)
void gemm_h(const float* __restrict__ bias, float* __restrict__ out_final)
{
    const __half* A = (MODE == 0) ? g_xh : g_yh;
    const __half* W = g_wh + (size_t)((MODE == 0) ? blockIdx.z : 3) * WELEM;

    __shared__ __align__(16) __half Asm[3][4096];
    __shared__ __align__(16) __half Bsm[3][4096];

    const int tid = threadIdx.x, lane = tid & 31, warp = tid >> 5;
    const int wm = warp & 1, wn = warp >> 1;
    const int g = lane >> 2, qq = lane & 3;
    const int bm = blockIdx.y * 128, bn = blockIdx.x * 128;

    const uint32_t sA = (uint32_t)__cvta_generic_to_shared(&Asm[0][0]);
    const uint32_t sB = (uint32_t)__cvta_generic_to_shared(&Bsm[0][0]);

    // fragment address constants (bytes; row stride 64B, 4 chunks, swz c^((row>>1)&3))
    const int lr8  = (lane & 7) + (lane & 8);      // 0..15
    const int lq   = lane >> 4;                    // 0..1
    const int swzA = (lr8 >> 1) & 3;
    const uint32_t aBase = sA + (uint32_t)(wm*64 + lr8) * 64;
    const int rB   = (lane & 7);
    const int swzB = (rB >> 1) & 3;
    const int cB   = lane >> 3;                    // 0..3
    const uint32_t bBase = sB + (uint32_t)(wn*32 + rB) * 64 + (uint32_t)((cB ^ swzB) << 4);

    float acc[4][4][4];
    #pragma unroll
    for (int i = 0; i < 4; ++i)
        #pragma unroll
        for (int j = 0; j < 4; ++j)
            #pragma unroll
            for (int r = 0; r < 4; ++r) acc[i][j][r] = 0.f;

    // loader
    const int ldr = tid >> 2, ldc = tid & 3;
    const int ldr2 = (tid + 256) >> 2, ldc2 = (tid + 256) & 3;
    const uint32_t dof1 = (uint32_t)(ldr*32  + ((ldc  ^ ((ldr >>1)&3)) << 3)) * 2;
    const uint32_t dof2 = (uint32_t)(ldr2*32 + ((ldc2 ^ ((ldr2>>1)&3)) << 3)) * 2;

    #define G_LOAD(st, kt) do {                                              \
        uint32_t so = (uint32_t)(st) * 8192;                                  \
        cp16(sA + so + dof1, A + (size_t)(bm + ldr )*Cc + (kt) + ldc *8);     \
        cp16(sA + so + dof2, A + (size_t)(bm + ldr2)*Cc + (kt) + ldc2*8);     \
        cp16(sB + so + dof1, W + (size_t)(bn + ldr )*Cc + (kt) + ldc *8);     \
        cp16(sB + so + dof2, W + (size_t)(bn + ldr2)*Cc + (kt) + ldc2*8);     \
    } while (0)

    G_LOAD(0, 0);  cp_commit();
    G_LOAD(1, 32); cp_commit();

    const int NIT = Cc / 32;
    int st = 0;
    for (int it = 0; it < NIT; ++it) {
        if (it + 1 < NIT) cp_wait<1>(); else cp_wait<0>();
        __syncthreads();
        if (it + 2 < NIT) {
            int st2 = st + 2; if (st2 >= 3) st2 -= 3;
            G_LOAD(st2, (it+2)*32);
            cp_commit();
        }

        const uint32_t so = (uint32_t)st * 8192;
        uint32_t bf[4][4];
        #pragma unroll
        for (int ni = 0; ni < 4; ++ni)
            ldsm4(bf[ni][0], bf[ni][1], bf[ni][2], bf[ni][3], bBase + so + (uint32_t)(ni*8*64));
        #pragma unroll
        for (int mi = 0; mi < 4; ++mi) {
            uint32_t a0[4], a1[4];
            ldsm4(a0[0], a0[1], a0[2], a0[3], aBase + so + (uint32_t)(mi*16*64) + (uint32_t)(((0 + lq) ^ swzA) << 4));
            ldsm4(a1[0], a1[1], a1[2], a1[3], aBase + so + (uint32_t)(mi*16*64) + (uint32_t)(((2 + lq) ^ swzA) << 4));
            #pragma unroll
            for (int ni = 0; ni < 4; ++ni) {
                mma16816(acc[mi][ni], a0, bf[ni][0], bf[ni][1]);
                mma16816(acc[mi][ni], a1, bf[ni][2], bf[ni][3]);
            }
        }
        if (++st >= 3) st -= 3;
    }
    #undef G_LOAD

    // Epilogue
    if (MODE == 0) {
        __half* outp = (blockIdx.z == 0) ? g_kh : (blockIdx.z == 1 ? g_qh : g_vh);
        const float sc = (blockIdx.z == 1) ? SCALE * LOG2E : 1.f;   // fold log2e into Q
        #pragma unroll
        for (int mi = 0; mi < 4; ++mi) {
            int r0 = bm + wm*64 + mi*16 + g;
            int b0 = r0 >> 11;
            int t0 = r0 & (Ts - 1);
            int t1 = (r0 + 8) & (Ts - 1);
            #pragma unroll
            for (int ni = 0; ni < 4; ++ni) {
                int c  = bn + wn*32 + ni*8 + 2*qq;
                int hh = c >> 6, dd = c & (Dh - 1);
                size_t base = ((size_t)(b0*Hh + hh)) * Ts;
                *reinterpret_cast<__half2*>(&outp[(base + t0)*Dh + dd]) =
                    __floats2half2_rn(acc[mi][ni][0]*sc, acc[mi][ni][1]*sc);
                *reinterpret_cast<__half2*>(&outp[(base + t1)*Dh + dd]) =
                    __floats2half2_rn(acc[mi][ni][2]*sc, acc[mi][ni][3]*sc);
            }
        }
    } else {
        #pragma unroll
        for (int mi = 0; mi < 4; ++mi) {
            int r0 = bm + wm*64 + mi*16 + g;
            #pragma unroll
            for (int ni = 0; ni < 4; ++ni) {
                int c = bn + wn*32 + ni*8 + 2*qq;
                float2 bb = *reinterpret_cast<const float2*>(&bias[c]);
                *reinterpret_cast<float2*>(&out_final[(size_t)r0 * Cc + c]) =
                    make_float2(acc[mi][ni][0] + bb.x, acc[mi][ni][1] + bb.y);
                *reinterpret_cast<float2*>(&out_final[(size_t)(r0 + 8) * Cc + c]) =
                    make_float2(acc[mi][ni][2] + bb.x, acc[mi][ni][3] + bb.y);
            }
        }
    }
}

// ---------------- Flash attention: fp16 mma + ldmatrix + cp.async ----------------
// CTA 256 thr / 8 warps; q-tile 128 (16 rows per warp); KV tiles 64, 2-stage.
// K/V smem rows = 64 halves (128B, 8 chunks); swizzle c ^ (row&7). P per-warp buffer.
__global__ __launch_bounds__(256)
void attn_h()
{
    const int bh = blockIdx.y, qt = blockIdx.x;
    const int tid = threadIdx.x, lane = tid & 31, wid = tid >> 5;
    const int g = lane >> 2, qq = lane & 3;

    const __half* qh = g_qh + (size_t)bh * Ts * Dh;
    const __half* kh = g_kh + (size_t)bh * Ts * Dh;
    const __half* vh = g_vh + (size_t)bh * Ts * Dh;

    __shared__ __align__(16) __half Ksm[2][4096];
    __shared__ __align__(16) __half Vsm[2][4096];
    __shared__ __align__(16) __half Psm[8192];      // 128 q-rows x 64

    const uint32_t sK = (uint32_t)__cvta_generic_to_shared(&Ksm[0][0]);
    const uint32_t sV = (uint32_t)__cvta_generic_to_shared(&Vsm[0][0]);
    const uint32_t sP = (uint32_t)__cvta_generic_to_shared(&Psm[0]);

    const int q0 = qt*128 + wid*16;

    // loader constants: 512 chunks per matrix, 2 per thread
    const int l7 = lane & 7;
    int lr[2], lc[2];
    uint32_t dof[2];
    #pragma unroll
    for (int m = 0; m < 2; ++m) {
        int id = tid + 256*m;
        lr[m] = id >> 3; lc[m] = id & 7;
        dof[m] = (uint32_t)(lr[m]*64 + ((lc[m] ^ (lr[m]&7)) << 3)) * 2;
    }
    #define KV_LOAD(st, kt) do {                                              \
        uint32_t so = (uint32_t)(st) * 8192;                                   \
        _Pragma("unroll")                                                      \
        for (int m = 0; m < 2; ++m) {                                          \
            cp16(sK + so + dof[m], kh + (size_t)((kt) + lr[m])*Dh + lc[m]*8);  \
            cp16(sV + so + dof[m], vh + (size_t)((kt) + lr[m])*Dh + lc[m]*8);  \
        }                                                                      \
    } while (0)

    KV_LOAD(0, 0);
    cp_commit();

    // Q fragments from global fp16 (pre-scaled by log2e/8)
    uint32_t qf[4][4];
    #pragma unroll
    for (int ks = 0; ks < 4; ++ks) {
        const __half* p0 = qh + (size_t)(q0 + g    )*Dh + ks*16 + 2*qq;
        const __half* p1 = qh + (size_t)(q0 + g + 8)*Dh + ks*16 + 2*qq;
        qf[ks][0] = *reinterpret_cast<const uint32_t*>(p0);
        qf[ks][1] = *reinterpret_cast<const uint32_t*>(p1);
        qf[ks][2] = *reinterpret_cast<const uint32_t*>(p0 + 8);
        qf[ks][3] = *reinterpret_cast<const uint32_t*>(p1 + 8);
    }

    float o[8][4];
    #pragma unroll
    for (int ni = 0; ni < 8; ++ni)
        #pragma unroll
        for (int r = 0; r < 4; ++r) o[ni][r] = 0.f;
    float m0 = -1e30f, m1 = -1e30f, l0 = 0.f, l1 = 0.f;

    // per-thread LDSM address constants
    const int lr8 = (lane & 7) + (lane & 8);
    const int lq  = lane >> 4;
    const uint32_t kBase = sK + (uint32_t)l7 * 128;
    const uint32_t vBase = sV + (uint32_t)((lane >> 3)*8 + l7) * 128;
    const uint32_t pBase = sP + (uint32_t)(wid*16 + lr8) * 128;
    const int kChunk = lane >> 3;

    const int NIT = Ts / 64;
    for (int it = 0; it < NIT; ++it) {
        if (it + 1 < NIT) { KV_LOAD((it+1)&1, (it+1)*64); cp_commit(); cp_wait<1>(); }
        else              { cp_wait<0>(); }
        __syncthreads();

        const uint32_t so = (uint32_t)(it & 1) * 8192;

        // S = Q K^T  (warp: 16 x 64), log2 domain
        float s[8][4];
        #pragma unroll
        for (int ni = 0; ni < 8; ++ni) {
            #pragma unroll
            for (int r = 0; r < 4; ++r) s[ni][r] = 0.f;
            uint32_t b0,b1,b2,b3,b4,b5,b6,b7;
            uint32_t base = kBase + so + (uint32_t)(ni*8*128);
            ldsm4(b0,b1,b2,b3, base + (uint32_t)(((kChunk    ) ^ l7) << 4));
            ldsm4(b4,b5,b6,b7, base + (uint32_t)(((kChunk + 4) ^ l7) << 4));
            mma16816(s[ni], qf[0], b0, b1);
            mma16816(s[ni], qf[1], b2, b3);
            mma16816(s[ni], qf[2], b4, b5);
            mma16816(s[ni], qf[3], b6, b7);
        }

        // Online softmax (base-2)
        float mt0 = m0, mt1 = m1;
        #pragma unroll
        for (int ni = 0; ni < 8; ++ni) {
            mt0 = fmaxf(mt0, fmaxf(s[ni][0], s[ni][1]));
            mt1 = fmaxf(mt1, fmaxf(s[ni][2], s[ni][3]));
        }
        mt0 = fmaxf(mt0, __shfl_xor_sync(0xffffffffu, mt0, 1));
        mt0 = fmaxf(mt0, __shfl_xor_sync(0xffffffffu, mt0, 2));
        mt1 = fmaxf(mt1, __shfl_xor_sync(0xffffffffu, mt1, 1));
        mt1 = fmaxf(mt1, __shfl_xor_sync(0xffffffffu, mt1, 2));
        float corr0 = dexp2(m0 - mt0);
        float corr1 = dexp2(m1 - mt1);
        m0 = mt0; m1 = mt1;

        float rs0 = 0.f, rs1 = 0.f;
        #pragma unroll
        for (int ni = 0; ni < 8; ++ni) {
            float p0 = dexp2(s[ni][0] - m0);
            float p1 = dexp2(s[ni][1] - m0);
            float p2 = dexp2(s[ni][2] - m1);
            float p3 = dexp2(s[ni][3] - m1);
            rs0 += p0 + p1;
            rs1 += p2 + p3;
            int idx0 = (wid*16 + g    )*64 + ((ni ^ g) << 3) + 2*qq;
            int idx1 = (wid*16 + g + 8)*64 + ((ni ^ g) << 3) + 2*qq;
            *reinterpret_cast<__half2*>(&Psm[idx0]) = __floats2half2_rn(p0, p1);
            *reinterpret_cast<__half2*>(&Psm[idx1]) = __floats2half2_rn(p2, p3);
        }
        rs0 += __shfl_xor_sync(0xffffffffu, rs0, 1);
        rs0 += __shfl_xor_sync(0xffffffffu, rs0, 2);
        rs1 += __shfl_xor_sync(0xffffffffu, rs1, 1);
        rs1 += __shfl_xor_sync(0xffffffffu, rs1, 2);
        l0 = l0 * corr0 + rs0;
        l1 = l1 * corr1 + rs1;

        #pragma unroll
        for (int ni = 0; ni < 8; ++ni) {
            o[ni][0] *= corr0; o[ni][1] *= corr0;
            o[ni][2] *= corr1; o[ni][3] *= corr1;
        }
        __syncwarp();

        // P fragments (A) from per-warp smem buffer
        uint32_t ap[4][4];
        #pragma unroll
        for (int ks = 0; ks < 4; ++ks)
            ldsm4(ap[ks][0], ap[ks][1], ap[ks][2], ap[ks][3],
                  pBase + (uint32_t)((((2*ks + lq)) ^ (lr8 & 7)) << 4));

        // O += P V  (V via ldmatrix.trans)
        #pragma unroll
        for (int ni = 0; ni < 8; ++ni) {
            uint32_t c0,c1,c2,c3,c4,c5,c6,c7;
            uint32_t vb = vBase + so + (uint32_t)((ni ^ l7) << 4);
            ldsm4t(c0,c1,c2,c3, vb);
            ldsm4t(c4,c5,c6,c7, vb + (uint32_t)(32*128));
            mma16816(o[ni], ap[0], c0, c1);
            mma16816(o[ni], ap[1], c2, c3);
            mma16816(o[ni], ap[2], c4, c5);
            mma16816(o[ni], ap[3], c6, c7);
        }
        __syncthreads();
    }
    #undef KV_LOAD

    // Write O/l -> g_yh [b][t][h*64+d] (fp16)
    const int b = bh / Hh, h = bh % Hh;
    const float inv0 = 1.f / l0, inv1 = 1.f / l1;
    const int r0 = q0 + g;
    #pragma unroll
    for (int ni = 0; ni < 8; ++ni) {
        int c = ni*8 + 2*qq;
        *reinterpret_cast<__half2*>(&g_yh[((size_t)(b*Ts + r0    ))*Cc + h*Dh + c]) =
            __floats2half2_rn(o[ni][0]*inv0, o[ni][1]*inv0);
        *reinterpret_cast<__half2*>(&g_yh[((size_t)(b*Ts + r0 + 8))*Cc + h*Dh + c]) =
            __floats2half2_rn(o[ni][2]*inv1, o[ni][3]*inv1);
    }
}

extern "C" void kernel_launch(void* const* d_in, const int* in_sizes, int n_in,
                              void* d_out, int out_size)
{
    const float* x  = (const float*)d_in[0];
    const float* Wk = (const float*)d_in[1];
    const float* Wq = (const float*)d_in[2];
    const float* Wv = (const float*)d_in[3];
    const float* Wp = (const float*)d_in[4];
    const float* bp = (const float*)d_in[5];
    float* out = (float*)d_out;

    const int nx8 = MROWS*Cc/8, nw8 = WELEM/8;
    const int ntot = nx8 + 4*nw8;
    f2h_all<<<(ntot + 255)/256, 256>>>(x, Wk, Wq, Wv, Wp, nx8, nw8);

    dim3 gridQKV(Cc/128, MROWS/128, 3);
    gemm_h<0><<<gridQKV, 256>>>(nullptr, nullptr);

    dim3 gridAtt(Ts/128, Bb*Hh);
    attn_h<<<gridAtt, 256>>>();

    dim3 gridOut(Cc/128, MROWS/128, 1);
    gemm_h<1><<<gridOut, 256>>>(bp, out);
}

// round 9
// speedup vs baseline: 1.2259x; 1.2259x over previous
#include <cuda_runtime.h>
#include <cuda_fp16.h>
#include <cstdint>

#define Bb 2
#define Ts 2048
#define Cc 1024
#define Hh 16
#define Dh 64
#define MROWS (Bb*Ts)   // 4096
#define SCALE 0.125f
#define LOG2E 1.4426950408889634f
#define WELEM (Cc*Cc)

// Scratch (allocation-free rule: __device__ globals)
__device__ __align__(16) __half g_xh[MROWS*Cc];
__device__ __align__(16) __half g_wh[4*WELEM];          // Wk, Wq, Wv, Wp (fp16)
__device__ __align__(16) __half g_qh[Bb*Hh*Ts*Dh];      // [b,h,t,d], pre-scaled by log2e/8
__device__ __align__(16) __half g_kh[Bb*Hh*Ts*Dh];
__device__ __align__(16) __half g_vh[Bb*Hh*Ts*Dh];
__device__ __align__(16) __half g_yh[MROWS*Cc];

__device__ __forceinline__ void cp16(uint32_t dst, const void* src) {
    asm volatile("cp.async.cg.shared.global [%0], [%1], 16;\n" :: "r"(dst), "l"(src));
}
__device__ __forceinline__ void cp_commit() { asm volatile("cp.async.commit_group;\n"); }
template<int N> __device__ __forceinline__ void cp_wait() {
    asm volatile("cp.async.wait_group %0;\n" :: "n"(N));
}
__device__ __forceinline__ void ldsm4(uint32_t& r0, uint32_t& r1, uint32_t& r2, uint32_t& r3, uint32_t a) {
    asm volatile("ldmatrix.sync.aligned.m8n8.x4.shared.b16 {%0,%1,%2,%3}, [%4];\n"
                 : "=r"(r0), "=r"(r1), "=r"(r2), "=r"(r3) : "r"(a));
}
__device__ __forceinline__ void ldsm4t(uint32_t& r0, uint32_t& r1, uint32_t& r2, uint32_t& r3, uint32_t a) {
    asm volatile("ldmatrix.sync.aligned.m8n8.x4.trans.shared.b16 {%0,%1,%2,%3}, [%4];\n"
                 : "=r"(r0), "=r"(r1), "=r"(r2), "=r"(r3) : "r"(a));
}
__device__ __forceinline__ void mma16816(float* c, const uint32_t* a, uint32_t b0, uint32_t b1) {
    asm volatile("mma.sync.aligned.m16n8k16.row.col.f32.f16.f16.f32 "
                 "{%0,%1,%2,%3}, {%4,%5,%6,%7}, {%8,%9}, {%0,%1,%2,%3};\n"
                 : "+f"(c[0]), "+f"(c[1]), "+f"(c[2]), "+f"(c[3])
                 : "r"(a[0]), "r"(a[1]), "r"(a[2]), "r"(a[3]), "r"(b0), "r"(b1));
}
__device__ __forceinline__ float dexp2(float x) {
    float r;
    asm("ex2.approx.f32 %0, %1;" : "=f"(r) : "f"(x));
    return r;
}
// pack two f32 -> f16x2 (lo in low half), one SASS cvt
__device__ __forceinline__ uint32_t packh2(float lo, float hi) {
    uint32_t r;
    asm("cvt.rn.f16x2.f32 %0, %1, %2;" : "=r"(r) : "f"(hi), "f"(lo));
    return r;
}

// ---------------- f32 -> f16 preconversion (single launch) ----------------
__global__ void f2h_all(const float* __restrict__ x,  const float* __restrict__ wk,
                        const float* __restrict__ wq, const float* __restrict__ wv,
                        const float* __restrict__ wp, int nx8, int nw8) {
    int i = blockIdx.x * blockDim.x + threadIdx.x;
    const float* s;
    __half* d;
    int off;
    if (i < nx8) { s = x; d = g_xh; off = i; }
    else {
        int j = i - nx8;
        int which = j / nw8;
        off = j - which * nw8;
        s = (which == 0) ? wk : (which == 1) ? wq : (which == 2) ? wv : wp;
        d = g_wh + (size_t)which * WELEM;
    }
    float4 a = reinterpret_cast<const float4*>(s)[2*off];
    float4 b = reinterpret_cast<const float4*>(s)[2*off+1];
    __half2* d2 = reinterpret_cast<__half2*>(d) + 4*off;
    d2[0] = __floats2half2_rn(a.x, a.y);
    d2[1] = __floats2half2_rn(a.z, a.w);
    d2[2] = __floats2half2_rn(b.x, b.y);
    d2[3] = __floats2half2_rn(b.z, b.w);
}

// ---------------- fp16 GEMM (round-4 measured-good config) ----------------
// Block 128x128, BK=32 halves, 2-stage cp.async, 8 warps 2(M)x4(N), warp 64x32.
template<int MODE>
__global__ __launch_bounds__(256, 2)
void gemm_h(const float* __restrict__ bias, float* __restrict__ out_final)
{
    const __half* A = (MODE == 0) ? g_xh : g_yh;
    const __half* W = g_wh + (size_t)((MODE == 0) ? blockIdx.z : 3) * WELEM;

    __shared__ __align__(16) __half Asm[2][4096];
    __shared__ __align__(16) __half Bsm[2][4096];

    const int tid = threadIdx.x, lane = tid & 31, warp = tid >> 5;
    const int wm = warp & 1, wn = warp >> 1;
    const int g = lane >> 2, qq = lane & 3;
    const int bm = blockIdx.y * 128, bn = blockIdx.x * 128;

    const uint32_t sA = (uint32_t)__cvta_generic_to_shared(&Asm[0][0]);
    const uint32_t sB = (uint32_t)__cvta_generic_to_shared(&Bsm[0][0]);

    const int lr8  = (lane & 7) + (lane & 8);
    const int lq   = lane >> 4;
    const int swzA = (lr8 >> 1) & 3;
    const uint32_t aBase = sA + (uint32_t)(wm*64 + lr8) * 64;
    const int rB   = (lane & 7);
    const int swzB = (rB >> 1) & 3;
    const int cB   = lane >> 3;
    const uint32_t bBase = sB + (uint32_t)(wn*32 + rB) * 64 + (uint32_t)((cB ^ swzB) << 4);

    float acc[4][4][4];
    #pragma unroll
    for (int i = 0; i < 4; ++i)
        #pragma unroll
        for (int j = 0; j < 4; ++j)
            #pragma unroll
            for (int r = 0; r < 4; ++r) acc[i][j][r] = 0.f;

    const int ldr = tid >> 2, ldc = tid & 3;
    const int ldr2 = (tid + 256) >> 2, ldc2 = (tid + 256) & 3;
    const uint32_t dof1 = (uint32_t)(ldr*32  + ((ldc  ^ ((ldr >>1)&3)) << 3)) * 2;
    const uint32_t dof2 = (uint32_t)(ldr2*32 + ((ldc2 ^ ((ldr2>>1)&3)) << 3)) * 2;

    #define G_LOAD(st, kt) do {                                              \
        uint32_t so = (uint32_t)(st) * 8192;                                  \
        cp16(sA + so + dof1, A + (size_t)(bm + ldr )*Cc + (kt) + ldc *8);     \
        cp16(sA + so + dof2, A + (size_t)(bm + ldr2)*Cc + (kt) + ldc2*8);     \
        cp16(sB + so + dof1, W + (size_t)(bn + ldr )*Cc + (kt) + ldc *8);     \
        cp16(sB + so + dof2, W + (size_t)(bn + ldr2)*Cc + (kt) + ldc2*8);     \
    } while (0)

    G_LOAD(0, 0);
    cp_commit();

    const int NIT = Cc / 32;
    for (int it = 0; it < NIT; ++it) {
        if (it + 1 < NIT) { G_LOAD((it+1)&1, (it+1)*32); cp_commit(); cp_wait<1>(); }
        else              { cp_wait<0>(); }
        __syncthreads();

        const uint32_t so = (uint32_t)(it & 1) * 8192;
        uint32_t bf[4][4];
        #pragma unroll
        for (int ni = 0; ni < 4; ++ni)
            ldsm4(bf[ni][0], bf[ni][1], bf[ni][2], bf[ni][3], bBase + so + (uint32_t)(ni*8*64));
        #pragma unroll
        for (int mi = 0; mi < 4; ++mi) {
            uint32_t a0[4], a1[4];
            ldsm4(a0[0], a0[1], a0[2], a0[3], aBase + so + (uint32_t)(mi*16*64) + (uint32_t)(((0 + lq) ^ swzA) << 4));
            ldsm4(a1[0], a1[1], a1[2], a1[3], aBase + so + (uint32_t)(mi*16*64) + (uint32_t)(((2 + lq) ^ swzA) << 4));
            #pragma unroll
            for (int ni = 0; ni < 4; ++ni) {
                mma16816(acc[mi][ni], a0, bf[ni][0], bf[ni][1]);
                mma16816(acc[mi][ni], a1, bf[ni][2], bf[ni][3]);
            }
        }
        __syncthreads();
    }
    #undef G_LOAD

    // Epilogue
    if (MODE == 0) {
        __half* outp = (blockIdx.z == 0) ? g_kh : (blockIdx.z == 1 ? g_qh : g_vh);
        const float sc = (blockIdx.z == 1) ? SCALE * LOG2E : 1.f;   // fold log2e into Q
        #pragma unroll
        for (int mi = 0; mi < 4; ++mi) {
            int r0 = bm + wm*64 + mi*16 + g;
            int b0 = r0 >> 11;
            int t0 = r0 & (Ts - 1);
            int t1 = (r0 + 8) & (Ts - 1);
            #pragma unroll
            for (int ni = 0; ni < 4; ++ni) {
                int c  = bn + wn*32 + ni*8 + 2*qq;
                int hh = c >> 6, dd = c & (Dh - 1);
                size_t base = ((size_t)(b0*Hh + hh)) * Ts;
                *reinterpret_cast<uint32_t*>(&outp[(base + t0)*Dh + dd]) =
                    packh2(acc[mi][ni][0]*sc, acc[mi][ni][1]*sc);
                *reinterpret_cast<uint32_t*>(&outp[(base + t1)*Dh + dd]) =
                    packh2(acc[mi][ni][2]*sc, acc[mi][ni][3]*sc);
            }
        }
    } else {
        #pragma unroll
        for (int mi = 0; mi < 4; ++mi) {
            int r0 = bm + wm*64 + mi*16 + g;
            #pragma unroll
            for (int ni = 0; ni < 4; ++ni) {
                int c = bn + wn*32 + ni*8 + 2*qq;
                float2 bb = *reinterpret_cast<const float2*>(&bias[c]);
                *reinterpret_cast<float2*>(&out_final[(size_t)r0 * Cc + c]) =
                    make_float2(acc[mi][ni][0] + bb.x, acc[mi][ni][1] + bb.y);
                *reinterpret_cast<float2*>(&out_final[(size_t)(r0 + 8) * Cc + c]) =
                    make_float2(acc[mi][ni][2] + bb.x, acc[mi][ni][3] + bb.y);
            }
        }
    }
}

// ---------------- Flash attention: fp16 mma, P in registers ----------------
// CTA 128 thr / 4 warps; q-tile 64 (16 rows/warp); KV tiles 64, 2-stage.
// S C-fragments -> exp2 -> packed directly as PV A-fragments (no smem P).
__global__ __launch_bounds__(128)
void attn_h()
{
    const int bh = blockIdx.y, qt = blockIdx.x;
    const int tid = threadIdx.x, lane = tid & 31, wid = tid >> 5;
    const int g = lane >> 2, qq = lane & 3;

    const __half* qh = g_qh + (size_t)bh * Ts * Dh;
    const __half* kh = g_kh + (size_t)bh * Ts * Dh;
    const __half* vh = g_vh + (size_t)bh * Ts * Dh;

    __shared__ __align__(16) __half Ksm[2][4096];
    __shared__ __align__(16) __half Vsm[2][4096];

    const uint32_t sK = (uint32_t)__cvta_generic_to_shared(&Ksm[0][0]);
    const uint32_t sV = (uint32_t)__cvta_generic_to_shared(&Vsm[0][0]);

    const int q0 = qt*64 + wid*16;

    // loader constants: 512 chunks per matrix, 4 per thread
    const int l7 = lane & 7;
    int lr[4], lc[4];
    uint32_t dof[4];
    #pragma unroll
    for (int m = 0; m < 4; ++m) {
        int id = tid + 128*m;
        lr[m] = id >> 3; lc[m] = id & 7;
        dof[m] = (uint32_t)(lr[m]*64 + ((lc[m] ^ (lr[m]&7)) << 3)) * 2;
    }
    #define KV_LOAD(st, kt) do {                                              \
        uint32_t so = (uint32_t)(st) * 8192;                                   \
        _Pragma("unroll")                                                      \
        for (int m = 0; m < 4; ++m) {                                          \
            cp16(sK + so + dof[m], kh + (size_t)((kt) + lr[m])*Dh + lc[m]*8);  \
            cp16(sV + so + dof[m], vh + (size_t)((kt) + lr[m])*Dh + lc[m]*8);  \
        }                                                                      \
    } while (0)

    KV_LOAD(0, 0);
    cp_commit();

    // Q fragments from global fp16 (pre-scaled by log2e/8)
    uint32_t qf[4][4];
    #pragma unroll
    for (int ks = 0; ks < 4; ++ks) {
        const __half* p0 = qh + (size_t)(q0 + g    )*Dh + ks*16 + 2*qq;
        const __half* p1 = qh + (size_t)(q0 + g + 8)*Dh + ks*16 + 2*qq;
        qf[ks][0] = *reinterpret_cast<const uint32_t*>(p0);
        qf[ks][1] = *reinterpret_cast<const uint32_t*>(p1);
        qf[ks][2] = *reinterpret_cast<const uint32_t*>(p0 + 8);
        qf[ks][3] = *reinterpret_cast<const uint32_t*>(p1 + 8);
    }

    float o[8][4];
    #pragma unroll
    for (int ni = 0; ni < 8; ++ni)
        #pragma unroll
        for (int r = 0; r < 4; ++r) o[ni][r] = 0.f;
    float m0 = -1e30f, m1 = -1e30f, l0 = 0.f, l1 = 0.f;

    const uint32_t kBase = sK + (uint32_t)l7 * 128;
    const uint32_t vBase = sV + (uint32_t)((lane >> 3)*8 + l7) * 128;
    const int kChunk = lane >> 3;

    const int NIT = Ts / 64;
    for (int it = 0; it < NIT; ++it) {
        if (it + 1 < NIT) { KV_LOAD((it+1)&1, (it+1)*64); cp_commit(); cp_wait<1>(); }
        else              { cp_wait<0>(); }
        __syncthreads();

        const uint32_t so = (uint32_t)(it & 1) * 8192;

        // S = Q K^T (warp: 16 x 64), log2 domain
        float s[8][4];
        #pragma unroll
        for (int ni = 0; ni < 8; ++ni) {
            #pragma unroll
            for (int r = 0; r < 4; ++r) s[ni][r] = 0.f;
            uint32_t b0,b1,b2,b3,b4,b5,b6,b7;
            uint32_t base = kBase + so + (uint32_t)(ni*8*128);
            ldsm4(b0,b1,b2,b3, base + (uint32_t)(((kChunk    ) ^ l7) << 4));
            ldsm4(b4,b5,b6,b7, base + (uint32_t)(((kChunk + 4) ^ l7) << 4));
            mma16816(s[ni], qf[0], b0, b1);
            mma16816(s[ni], qf[1], b2, b3);
            mma16816(s[ni], qf[2], b4, b5);
            mma16816(s[ni], qf[3], b6, b7);
        }

        // Online softmax (base-2)
        float mt0 = m0, mt1 = m1;
        #pragma unroll
        for (int ni = 0; ni < 8; ++ni) {
            mt0 = fmaxf(mt0, fmaxf(s[ni][0], s[ni][1]));
            mt1 = fmaxf(mt1, fmaxf(s[ni][2], s[ni][3]));
        }
        mt0 = fmaxf(mt0, __shfl_xor_sync(0xffffffffu, mt0, 1));
        mt0 = fmaxf(mt0, __shfl_xor_sync(0xffffffffu, mt0, 2));
        mt1 = fmaxf(mt1, __shfl_xor_sync(0xffffffffu, mt1, 1));
        mt1 = fmaxf(mt1, __shfl_xor_sync(0xffffffffu, mt1, 2));
        float corr0 = dexp2(m0 - mt0);
        float corr1 = dexp2(m1 - mt1);
        m0 = mt0; m1 = mt1;

        // exp2 -> pack P directly into PV A-fragments (registers only)
        uint32_t ap[4][4];
        float rs0 = 0.f, rs1 = 0.f;
        #pragma unroll
        for (int ks = 0; ks < 4; ++ks) {
            float p0a = dexp2(s[2*ks  ][0] - m0), p1a = dexp2(s[2*ks  ][1] - m0);
            float p2a = dexp2(s[2*ks  ][2] - m1), p3a = dexp2(s[2*ks  ][3] - m1);
            float p0b = dexp2(s[2*ks+1][0] - m0), p1b = dexp2(s[2*ks+1][1] - m0);
            float p2b = dexp2(s[2*ks+1][2] - m1), p3b = dexp2(s[2*ks+1][3] - m1);
            rs0 += (p0a + p1a) + (p0b + p1b);
            rs1 += (p2a + p3a) + (p2b + p3b);
            ap[ks][0] = packh2(p0a, p1a);
            ap[ks][1] = packh2(p2a, p3a);
            ap[ks][2] = packh2(p0b, p1b);
            ap[ks][3] = packh2(p2b, p3b);
        }
        rs0 += __shfl_xor_sync(0xffffffffu, rs0, 1);
        rs0 += __shfl_xor_sync(0xffffffffu, rs0, 2);
        rs1 += __shfl_xor_sync(0xffffffffu, rs1, 1);
        rs1 += __shfl_xor_sync(0xffffffffu, rs1, 2);
        l0 = l0 * corr0 + rs0;
        l1 = l1 * corr1 + rs1;

        #pragma unroll
        for (int ni = 0; ni < 8; ++ni) {
            o[ni][0] *= corr0; o[ni][1] *= corr0;
            o[ni][2] *= corr1; o[ni][3] *= corr1;
        }

        // O += P V  (V via ldmatrix.trans)
        #pragma unroll
        for (int ni = 0; ni < 8; ++ni) {
            uint32_t c0,c1,c2,c3,c4,c5,c6,c7;
            uint32_t vb = vBase + so + (uint32_t)((ni ^ l7) << 4);
            ldsm4t(c0,c1,c2,c3, vb);
            ldsm4t(c4,c5,c6,c7, vb + (uint32_t)(32*128));
            mma16816(o[ni], ap[0], c0, c1);
            mma16816(o[ni], ap[1], c2, c3);
            mma16816(o[ni], ap[2], c4, c5);
            mma16816(o[ni], ap[3], c6, c7);
        }
        __syncthreads();
    }
    #undef KV_LOAD

    // Write O/l -> g_yh [b][t][h*64+d] (fp16)
    const int b = bh / Hh, h = bh % Hh;
    const float inv0 = 1.f / l0, inv1 = 1.f / l1;
    const int r0 = q0 + g;
    #pragma unroll
    for (int ni = 0; ni < 8; ++ni) {
        int c = ni*8 + 2*qq;
        *reinterpret_cast<uint32_t*>(&g_yh[((size_t)(b*Ts + r0    ))*Cc + h*Dh + c]) =
            packh2(o[ni][0]*inv0, o[ni][1]*inv0);
        *reinterpret_cast<uint32_t*>(&g_yh[((size_t)(b*Ts + r0 + 8))*Cc + h*Dh + c]) =
            packh2(o[ni][2]*inv1, o[ni][3]*inv1);
    }
}

extern "C" void kernel_launch(void* const* d_in, const int* in_sizes, int n_in,
                              void* d_out, int out_size)
{
    const float* x  = (const float*)d_in[0];
    const float* Wk = (const float*)d_in[1];
    const float* Wq = (const float*)d_in[2];
    const float* Wv = (const float*)d_in[3];
    const float* Wp = (const float*)d_in[4];
    const float* bp = (const float*)d_in[5];
    float* out = (float*)d_out;

    const int nx8 = MROWS*Cc/8, nw8 = WELEM/8;
    const int ntot = nx8 + 4*nw8;
    f2h_all<<<(ntot + 255)/256, 256>>>(x, Wk, Wq, Wv, Wp, nx8, nw8);

    dim3 gridQKV(Cc/128, MROWS/128, 3);
    gemm_h<0><<<gridQKV, 256>>>(nullptr, nullptr);

    dim3 gridAtt(Ts/64, Bb*Hh);
    attn_h<<<gridAtt, 128>>>();

    dim3 gridOut(Cc/128, MROWS/128, 1);
    gemm_h<1><<<gridOut, 256>>>(bp, out);
}